// round 11
// baseline (speedup 1.0000x reference)
#include <cuda_runtime.h>
#include <cuda_bf16.h>
#include <stdint.h>

#define NUM_NODES 10000
#define NUM_EDGES 640000
#define GNN_IN    128
#define HID       256

// Per-node tables: PAB[node][0:256]  = x[node]@W1[0:128] + b1  (b1 folded)
//                  PAB[node][256:512] = x[node]@W1[128:256]
__device__ __align__(16) __nv_bfloat16 g_pab[NUM_NODES * 512];

// ---------------------------------------------------------------------------
// Packed f32x2 helpers (Blackwell FFMA2 path)
// ---------------------------------------------------------------------------
__device__ __forceinline__ unsigned long long pack_f32x2(float lo, float hi) {
    unsigned long long r;
    asm("mov.b64 %0, {%1, %2};" : "=l"(r) : "f"(lo), "f"(hi));
    return r;
}
__device__ __forceinline__ void unpack_f32x2(unsigned long long v, float& lo, float& hi) {
    asm("mov.b64 {%0, %1}, %2;" : "=f"(lo), "=f"(hi) : "l"(v));
}
__device__ __forceinline__ unsigned long long fma_f32x2(
    unsigned long long a, unsigned long long b, unsigned long long c) {
    unsigned long long r;
    asm("fma.rn.f32x2 %0, %1, %2, %3;" : "=l"(r) : "l"(a), "l"(b), "l"(c));
    return r;
}

// ---------------------------------------------------------------------------
// Kernel 1: precompute GEMM on tensor cores (tf32 mma.sync.m16n8k8).
// Warp (block b, warp w) computes PAB rows [16b,16b+16) x cols [64w,64w+64).
// M=10000=625*16, N=512=8*64, K=128=16*8 -> exact tiling, no bounds checks.
// ---------------------------------------------------------------------------
__device__ __forceinline__ uint32_t f32_to_tf32(float f) {
    uint32_t r;
    asm("cvt.rna.tf32.f32 %0, %1;" : "=r"(r) : "f"(f));
    return r;
}

__global__ __launch_bounds__(256) void precompute_mma(
    const float* __restrict__ x, const float* __restrict__ w1,
    const float* __restrict__ b1)
{
    const int warp = threadIdx.x >> 5;       // 0..7  -> n-tile of 64
    const int lane = threadIdx.x & 31;
    const int g    = lane >> 2;               // group id 0..7
    const int t    = lane & 3;                // thread-in-group 0..3

    const int m0 = blockIdx.x * 16;
    const int n0 = warp * 64;

    // Wbig[k][n]: n<256 -> w1[k*HID + n]; n>=256 -> w1[(128+k)*HID + (n-256)].
    // Each 64-col warp tile lies entirely in one region.
    const float* wbase = (n0 < 256) ? (w1 + n0) : (w1 + 128 * HID + (n0 - 256));

    float c[8][4];
#pragma unroll
    for (int nc = 0; nc < 8; nc++)
#pragma unroll
        for (int i = 0; i < 4; i++) c[nc][i] = 0.f;

    const float* arow0 = x + (size_t)(m0 + g)     * GNN_IN;
    const float* arow1 = x + (size_t)(m0 + g + 8) * GNN_IN;

#pragma unroll
    for (int ks = 0; ks < 16; ks++) {
        const int k0 = ks * 8;
        // A fragment (16x8 tf32): a0:(g,t) a1:(g+8,t) a2:(g,t+4) a3:(g+8,t+4)
        uint32_t a0 = f32_to_tf32(arow0[k0 + t]);
        uint32_t a1 = f32_to_tf32(arow1[k0 + t]);
        uint32_t a2 = f32_to_tf32(arow0[k0 + t + 4]);
        uint32_t a3 = f32_to_tf32(arow1[k0 + t + 4]);

#pragma unroll
        for (int nc = 0; nc < 8; nc++) {
            // B fragment (8x8 tf32, col-major view): b0:(k=t, n=g) b1:(k=t+4, n=g)
            uint32_t b0 = f32_to_tf32(wbase[(size_t)(k0 + t)     * HID + nc * 8 + g]);
            uint32_t b1v = f32_to_tf32(wbase[(size_t)(k0 + t + 4) * HID + nc * 8 + g]);
            asm("mma.sync.aligned.m16n8k8.row.col.f32.tf32.tf32.f32 "
                "{%0,%1,%2,%3}, {%4,%5,%6,%7}, {%8,%9}, {%0,%1,%2,%3};"
                : "+f"(c[nc][0]), "+f"(c[nc][1]), "+f"(c[nc][2]), "+f"(c[nc][3])
                : "r"(a0), "r"(a1), "r"(a2), "r"(a3), "r"(b0), "r"(b1v));
        }
    }

    // Epilogue: c0:(row g, col 2t) c1:(g,2t+1) c2:(g+8,2t) c3:(g+8,2t+1)
    // Fold b1 into the PA half (global cols < 256).
#pragma unroll
    for (int nc = 0; nc < 8; nc++) {
        const int col = n0 + nc * 8 + 2 * t;
        float ba0 = 0.f, ba1 = 0.f;
        if (n0 < 256) { ba0 = b1[col]; ba1 = b1[col + 1]; }

        __nv_bfloat162 p0, p1;
        p0.x = __float2bfloat16_rn(c[nc][0] + ba0);
        p0.y = __float2bfloat16_rn(c[nc][1] + ba1);
        p1.x = __float2bfloat16_rn(c[nc][2] + ba0);
        p1.y = __float2bfloat16_rn(c[nc][3] + ba1);

        *(__nv_bfloat162*)(g_pab + (size_t)(m0 + g)     * 512 + col) = p0;
        *(__nv_bfloat162*)(g_pab + (size_t)(m0 + g + 8) * 512 + col) = p1;
    }
}

// ---------------------------------------------------------------------------
// Kernel 2: warp per edge pair; deferred-reduction pipeline (R9, best: 104.9us)
// ---------------------------------------------------------------------------
__device__ __forceinline__ uint4 gatherA(int node, int j0) {
    return *(const uint4*)(g_pab + (size_t)node * 512 + j0);
}
__device__ __forceinline__ uint4 gatherB(int node, int j0) {
    return *(const uint4*)(g_pab + (size_t)node * 512 + 256 + j0);
}

__device__ __forceinline__ float edge_mlp(
    uint4 pa, uint4 pb, float4 d,
    const unsigned long long wcp[4][4], const float w2r[8])
{
    unsigned long long dd0 = pack_f32x2(d.x, d.x);
    unsigned long long dd1 = pack_f32x2(d.y, d.y);
    unsigned long long dd2 = pack_f32x2(d.z, d.z);
    unsigned long long dd3 = pack_f32x2(d.w, d.w);

    const unsigned* A = (const unsigned*)&pa;
    const unsigned* B = (const unsigned*)&pb;
    float accL = 0.f, accH = 0.f;
#pragma unroll
    for (int p = 0; p < 4; p++) {
        __nv_bfloat162 av = *(const __nv_bfloat162*)&A[p];
        __nv_bfloat162 bv = *(const __nv_bfloat162*)&B[p];
        __nv_bfloat162 sv = __hadd2(av, bv);
        unsigned w = *(const unsigned*)&sv;
        float lo = __uint_as_float(w << 16);
        float hi = __uint_as_float(w & 0xffff0000u);
        unsigned long long t2 = pack_f32x2(lo, hi);
        t2 = fma_f32x2(dd0, wcp[0][p], t2);
        t2 = fma_f32x2(dd1, wcp[1][p], t2);
        t2 = fma_f32x2(dd2, wcp[2][p], t2);
        t2 = fma_f32x2(dd3, wcp[3][p], t2);
        float t0, t1;
        unpack_f32x2(t2, t0, t1);
        t0 = fmaxf(t0, 0.f);
        t1 = fmaxf(t1, 0.f);
        accL = fmaf(t0, w2r[2 * p], accL);
        accH = fmaf(t1, w2r[2 * p + 1], accH);
    }
    return accL + accH;
}

__device__ __forceinline__ void reduce_store(
    float ra0, float ra1, int re, int lane, float bias2, float* out)
{
    float s0 = ra0 + __shfl_xor_sync(0xffffffffu, ra0, 16);
    float s1 = ra1 + __shfl_xor_sync(0xffffffffu, ra1, 16);
    float c  = (lane < 16) ? s0 : s1;
    c += __shfl_xor_sync(0xffffffffu, c, 8);
    c += __shfl_xor_sync(0xffffffffu, c, 4);
    c += __shfl_xor_sync(0xffffffffu, c, 2);
    c += __shfl_xor_sync(0xffffffffu, c, 1);
    if ((lane & 15) == 0) {
        float z = c + bias2;
        out[re + (lane >> 4)] = 1.f / (1.f + __expf(-z));
    }
}

__global__ __launch_bounds__(128, 4) void edge_kernel(
    const int*   __restrict__ edge_index,
    const float* __restrict__ edge_dist,
    const float* __restrict__ w1,
    const float* __restrict__ w2,
    const float* __restrict__ b2,
    float* __restrict__ out)
{
    const int lane   = threadIdx.x & 31;
    const int warp   = blockIdx.x * (blockDim.x >> 5) + (threadIdx.x >> 5);
    const int nwarps = gridDim.x * (blockDim.x >> 5);
    const int j0     = lane * 8;

    unsigned long long wcp[4][4];
    float w2r[8];
#pragma unroll
    for (int i = 0; i < 8; i++) w2r[i] = w2[j0 + i];
#pragma unroll
    for (int r = 0; r < 4; r++)
#pragma unroll
        for (int p = 0; p < 4; p++)
            wcp[r][p] = pack_f32x2(w1[(size_t)(256 + r) * HID + j0 + 2 * p],
                                   w1[(size_t)(256 + r) * HID + j0 + 2 * p + 1]);
    const float bias2 = b2[0];

    const int stride = nwarps * 2;
    int ec = warp * 2;
    if (ec >= NUM_EDGES) return;

    const int2*   idx2  = (const int2*)edge_index;
    const float4* dist4 = (const float4*)edge_dist;

    int en  = ec + stride;
    int enc = (en < NUM_EDGES - 2) ? en : (NUM_EDGES - 2);
    int2 ia = idx2[ec], ib = idx2[ec + 1];
    int2 ja = idx2[enc], jb = idx2[enc + 1];

    uint4 pa0 = gatherA(ia.x, j0), pb0 = gatherB(ia.y, j0);
    uint4 pa1 = gatherA(ib.x, j0), pb1 = gatherB(ib.y, j0);
    float4 da0 = dist4[ec], db0 = dist4[ec + 1];

    uint4 qa0 = gatherA(ja.x, j0), qb0 = gatherB(ja.y, j0);
    uint4 qa1 = gatherA(jb.x, j0), qb1 = gatherB(jb.y, j0);
    float4 ea0 = dist4[enc], eb0 = dist4[enc + 1];

    int e2  = en + stride;
    int e2c = (e2 < NUM_EDGES - 2) ? e2 : (NUM_EDGES - 2);
    ja = idx2[e2c];  jb = idx2[e2c + 1];

    float ra0 = edge_mlp(pa0, pb0, da0, wcp, w2r);
    float ra1 = edge_mlp(pa1, pb1, db0, wcp, w2r);
    int   re  = ec;

    ec = en;
    if (ec >= NUM_EDGES) {
        reduce_store(ra0, ra1, re, lane, bias2, out);
        return;
    }
    en = e2;  enc = e2c;

    for (;;) {
        // ---- half A: gathers->set0(en); MLP from setQ(ec); reduce (re) ----
        pa0 = gatherA(ja.x, j0);  pb0 = gatherB(ja.y, j0);
        pa1 = gatherA(jb.x, j0);  pb1 = gatherB(jb.y, j0);
        da0 = dist4[enc];  db0 = dist4[enc + 1];
        {
            int e3  = en + stride;
            int e3c = (e3 < NUM_EDGES - 2) ? e3 : (NUM_EDGES - 2);
            ja = idx2[e3c];  jb = idx2[e3c + 1];

            float a0 = edge_mlp(qa0, qb0, ea0, wcp, w2r);
            float a1 = edge_mlp(qa1, qb1, eb0, wcp, w2r);
            reduce_store(ra0, ra1, re, lane, bias2, out);
            ra0 = a0;  ra1 = a1;  re = ec;

            ec = en;
            if (ec >= NUM_EDGES) break;
            en = e3;  enc = e3c;
        }

        // ---- half B: gathers->setQ(en); MLP from set0(ec); reduce (re) ----
        qa0 = gatherA(ja.x, j0);  qb0 = gatherB(ja.y, j0);
        qa1 = gatherA(jb.x, j0);  qb1 = gatherB(jb.y, j0);
        ea0 = dist4[enc];  eb0 = dist4[enc + 1];
        {
            int e3  = en + stride;
            int e3c = (e3 < NUM_EDGES - 2) ? e3 : (NUM_EDGES - 2);
            ja = idx2[e3c];  jb = idx2[e3c + 1];

            float a0 = edge_mlp(pa0, pb0, da0, wcp, w2r);
            float a1 = edge_mlp(pa1, pb1, db0, wcp, w2r);
            reduce_store(ra0, ra1, re, lane, bias2, out);
            ra0 = a0;  ra1 = a1;  re = ec;

            ec = en;
            if (ec >= NUM_EDGES) break;
            en = e3;  enc = e3c;
        }
    }

    reduce_store(ra0, ra1, re, lane, bias2, out);
}

// ---------------------------------------------------------------------------
extern "C" void kernel_launch(void* const* d_in, const int* in_sizes, int n_in,
                              void* d_out, int out_size) {
    const float* x          = (const float*)d_in[0];
    const int*   edge_index = (const int*)d_in[1];
    const float* edge_dist  = (const float*)d_in[2];
    const float* w1         = (const float*)d_in[3];
    const float* b1         = (const float*)d_in[4];
    const float* w2         = (const float*)d_in[5];
    const float* b2         = (const float*)d_in[6];
    float*       out        = (float*)d_out;

    precompute_mma<<<NUM_NODES / 16, 256>>>(x, w1, b1);

    edge_kernel<<<2368, 128>>>(edge_index, edge_dist, w1, w2, b2, out);
}

// round 12
// speedup vs baseline: 1.0787x; 1.0787x over previous
#include <cuda_runtime.h>
#include <cuda_bf16.h>
#include <stdint.h>

#define NUM_NODES 10000
#define NUM_EDGES 640000
#define GNN_IN    128
#define HID       256

// Per-node tables: PAB[node][0:256]  = x[node]@W1[0:128] + b1  (b1 folded)
//                  PAB[node][256:512] = x[node]@W1[128:256]
__device__ __align__(16) __nv_bfloat16 g_pab[NUM_NODES * 512];

// ---------------------------------------------------------------------------
// Packed f32x2 helpers
// ---------------------------------------------------------------------------
__device__ __forceinline__ unsigned long long pack_f32x2(float lo, float hi) {
    unsigned long long r;
    asm("mov.b64 %0, {%1, %2};" : "=l"(r) : "f"(lo), "f"(hi));
    return r;
}
__device__ __forceinline__ void unpack_f32x2(unsigned long long v, float& lo, float& hi) {
    asm("mov.b64 {%0, %1}, %2;" : "=f"(lo), "=f"(hi) : "l"(v));
}
__device__ __forceinline__ unsigned long long fma_f32x2(
    unsigned long long a, unsigned long long b, unsigned long long c) {
    unsigned long long r;
    asm("fma.rn.f32x2 %0, %1, %2, %3;" : "=l"(r) : "l"(a), "l"(b), "l"(c));
    return r;
}
__device__ __forceinline__ uint32_t f32_to_tf32(float f) {
    uint32_t r;
    asm("cvt.rna.tf32.f32 %0, %1;" : "=r"(r) : "f"(f));
    return r;
}

// ---------------------------------------------------------------------------
// Kernel 1: precompute GEMM on tensor cores, B staged in smem.
// Grid (8, 79): blockIdx.x -> 64-col N tile, blockIdx.y -> 128-row M tile.
// 8 warps/block; warp w owns rows [m0+16w, m0+16w+16).
// Ws padded to 68 floats/row: LDS bank = (4t+g)&31, conflict-free; rows
// 272B so 16B alignment holds for float4 staging.
// ---------------------------------------------------------------------------
__global__ __launch_bounds__(256) void precompute_mma(
    const float* __restrict__ x, const float* __restrict__ w1,
    const float* __restrict__ b1)
{
    __shared__ float Ws[128][68];

    const int tid  = threadIdx.x;
    const int warp = tid >> 5;
    const int lane = tid & 31;
    const int g    = lane >> 2;    // 0..7
    const int t    = lane & 3;     // 0..3

    const int n0 = blockIdx.x * 64;
    const int m0 = blockIdx.y * 128 + warp * 16;

    // Wbig region for this 64-col tile (each tile lies fully in one region).
    const float* wbase = (n0 < 256) ? (w1 + n0) : (w1 + 128 * HID + (n0 - 256));

    // Cooperative stage: 128 k-rows x 64 cols = 2048 float4, 8 per thread.
#pragma unroll
    for (int i = 0; i < 8; i++) {
        int idx4 = i * 256 + tid;         // 0..2047
        int row  = idx4 >> 4;             // 16 float4 per row
        int c4   = idx4 & 15;
        float4 v = *(const float4*)(wbase + (size_t)row * HID + c4 * 4);
        *(float4*)&Ws[row][c4 * 4] = v;
    }
    __syncthreads();

    // A row pointers (clamped for the partial last M tile).
    const int r0 = m0 + g, r1 = m0 + g + 8;
    const float* arow0 = x + (size_t)min(r0, NUM_NODES - 1) * GNN_IN;
    const float* arow1 = x + (size_t)min(r1, NUM_NODES - 1) * GNN_IN;

    float c[8][4];
#pragma unroll
    for (int nc = 0; nc < 8; nc++)
#pragma unroll
        for (int i = 0; i < 4; i++) c[nc][i] = 0.f;

#pragma unroll
    for (int ks = 0; ks < 16; ks++) {
        const int k0 = ks * 8;
        uint32_t a0 = f32_to_tf32(arow0[k0 + t]);
        uint32_t a1 = f32_to_tf32(arow1[k0 + t]);
        uint32_t a2 = f32_to_tf32(arow0[k0 + t + 4]);
        uint32_t a3 = f32_to_tf32(arow1[k0 + t + 4]);

#pragma unroll
        for (int nc = 0; nc < 8; nc++) {
            uint32_t b0 = f32_to_tf32(Ws[k0 + t][nc * 8 + g]);
            uint32_t b1v = f32_to_tf32(Ws[k0 + t + 4][nc * 8 + g]);
            asm("mma.sync.aligned.m16n8k8.row.col.f32.tf32.tf32.f32 "
                "{%0,%1,%2,%3}, {%4,%5,%6,%7}, {%8,%9}, {%0,%1,%2,%3};"
                : "+f"(c[nc][0]), "+f"(c[nc][1]), "+f"(c[nc][2]), "+f"(c[nc][3])
                : "r"(a0), "r"(a1), "r"(a2), "r"(a3), "r"(b0), "r"(b1v));
        }
    }

    // Epilogue: c0:(r0, col 2t) c1:(r0, 2t+1) c2:(r1, 2t) c3:(r1, 2t+1).
#pragma unroll
    for (int nc = 0; nc < 8; nc++) {
        const int col = n0 + nc * 8 + 2 * t;
        float ba0 = 0.f, ba1 = 0.f;
        if (n0 < 256) { ba0 = b1[col]; ba1 = b1[col + 1]; }

        if (r0 < NUM_NODES) {
            __nv_bfloat162 p;
            p.x = __float2bfloat16_rn(c[nc][0] + ba0);
            p.y = __float2bfloat16_rn(c[nc][1] + ba1);
            *(__nv_bfloat162*)(g_pab + (size_t)r0 * 512 + col) = p;
        }
        if (r1 < NUM_NODES) {
            __nv_bfloat162 p;
            p.x = __float2bfloat16_rn(c[nc][2] + ba0);
            p.y = __float2bfloat16_rn(c[nc][3] + ba1);
            *(__nv_bfloat162*)(g_pab + (size_t)r1 * 512 + col) = p;
        }
    }
}

// ---------------------------------------------------------------------------
// Kernel 2: warp per edge pair; deferred-reduction pipeline (R9, ~105us)
// ---------------------------------------------------------------------------
__device__ __forceinline__ uint4 gatherA(int node, int j0) {
    return *(const uint4*)(g_pab + (size_t)node * 512 + j0);
}
__device__ __forceinline__ uint4 gatherB(int node, int j0) {
    return *(const uint4*)(g_pab + (size_t)node * 512 + 256 + j0);
}

__device__ __forceinline__ float edge_mlp(
    uint4 pa, uint4 pb, float4 d,
    const unsigned long long wcp[4][4], const float w2r[8])
{
    unsigned long long dd0 = pack_f32x2(d.x, d.x);
    unsigned long long dd1 = pack_f32x2(d.y, d.y);
    unsigned long long dd2 = pack_f32x2(d.z, d.z);
    unsigned long long dd3 = pack_f32x2(d.w, d.w);

    const unsigned* A = (const unsigned*)&pa;
    const unsigned* B = (const unsigned*)&pb;
    float accL = 0.f, accH = 0.f;
#pragma unroll
    for (int p = 0; p < 4; p++) {
        __nv_bfloat162 av = *(const __nv_bfloat162*)&A[p];
        __nv_bfloat162 bv = *(const __nv_bfloat162*)&B[p];
        __nv_bfloat162 sv = __hadd2(av, bv);
        unsigned w = *(const unsigned*)&sv;
        float lo = __uint_as_float(w << 16);
        float hi = __uint_as_float(w & 0xffff0000u);
        unsigned long long t2 = pack_f32x2(lo, hi);
        t2 = fma_f32x2(dd0, wcp[0][p], t2);
        t2 = fma_f32x2(dd1, wcp[1][p], t2);
        t2 = fma_f32x2(dd2, wcp[2][p], t2);
        t2 = fma_f32x2(dd3, wcp[3][p], t2);
        float t0, t1;
        unpack_f32x2(t2, t0, t1);
        t0 = fmaxf(t0, 0.f);
        t1 = fmaxf(t1, 0.f);
        accL = fmaf(t0, w2r[2 * p], accL);
        accH = fmaf(t1, w2r[2 * p + 1], accH);
    }
    return accL + accH;
}

__device__ __forceinline__ void reduce_store(
    float ra0, float ra1, int re, int lane, float bias2, float* out)
{
    float s0 = ra0 + __shfl_xor_sync(0xffffffffu, ra0, 16);
    float s1 = ra1 + __shfl_xor_sync(0xffffffffu, ra1, 16);
    float c  = (lane < 16) ? s0 : s1;
    c += __shfl_xor_sync(0xffffffffu, c, 8);
    c += __shfl_xor_sync(0xffffffffu, c, 4);
    c += __shfl_xor_sync(0xffffffffu, c, 2);
    c += __shfl_xor_sync(0xffffffffu, c, 1);
    if ((lane & 15) == 0) {
        float z = c + bias2;
        out[re + (lane >> 4)] = 1.f / (1.f + __expf(-z));
    }
}

__global__ __launch_bounds__(128, 4) void edge_kernel(
    const int*   __restrict__ edge_index,
    const float* __restrict__ edge_dist,
    const float* __restrict__ w1,
    const float* __restrict__ w2,
    const float* __restrict__ b2,
    float* __restrict__ out)
{
    const int lane   = threadIdx.x & 31;
    const int warp   = blockIdx.x * (blockDim.x >> 5) + (threadIdx.x >> 5);
    const int nwarps = gridDim.x * (blockDim.x >> 5);
    const int j0     = lane * 8;

    unsigned long long wcp[4][4];
    float w2r[8];
#pragma unroll
    for (int i = 0; i < 8; i++) w2r[i] = w2[j0 + i];
#pragma unroll
    for (int r = 0; r < 4; r++)
#pragma unroll
        for (int p = 0; p < 4; p++)
            wcp[r][p] = pack_f32x2(w1[(size_t)(256 + r) * HID + j0 + 2 * p],
                                   w1[(size_t)(256 + r) * HID + j0 + 2 * p + 1]);
    const float bias2 = b2[0];

    const int stride = nwarps * 2;
    int ec = warp * 2;
    if (ec >= NUM_EDGES) return;

    const int2*   idx2  = (const int2*)edge_index;
    const float4* dist4 = (const float4*)edge_dist;

    int en  = ec + stride;
    int enc = (en < NUM_EDGES - 2) ? en : (NUM_EDGES - 2);
    int2 ia = idx2[ec], ib = idx2[ec + 1];
    int2 ja = idx2[enc], jb = idx2[enc + 1];

    uint4 pa0 = gatherA(ia.x, j0), pb0 = gatherB(ia.y, j0);
    uint4 pa1 = gatherA(ib.x, j0), pb1 = gatherB(ib.y, j0);
    float4 da0 = dist4[ec], db0 = dist4[ec + 1];

    uint4 qa0 = gatherA(ja.x, j0), qb0 = gatherB(ja.y, j0);
    uint4 qa1 = gatherA(jb.x, j0), qb1 = gatherB(jb.y, j0);
    float4 ea0 = dist4[enc], eb0 = dist4[enc + 1];

    int e2  = en + stride;
    int e2c = (e2 < NUM_EDGES - 2) ? e2 : (NUM_EDGES - 2);
    ja = idx2[e2c];  jb = idx2[e2c + 1];

    float ra0 = edge_mlp(pa0, pb0, da0, wcp, w2r);
    float ra1 = edge_mlp(pa1, pb1, db0, wcp, w2r);
    int   re  = ec;

    ec = en;
    if (ec >= NUM_EDGES) {
        reduce_store(ra0, ra1, re, lane, bias2, out);
        return;
    }
    en = e2;  enc = e2c;

    for (;;) {
        pa0 = gatherA(ja.x, j0);  pb0 = gatherB(ja.y, j0);
        pa1 = gatherA(jb.x, j0);  pb1 = gatherB(jb.y, j0);
        da0 = dist4[enc];  db0 = dist4[enc + 1];
        {
            int e3  = en + stride;
            int e3c = (e3 < NUM_EDGES - 2) ? e3 : (NUM_EDGES - 2);
            ja = idx2[e3c];  jb = idx2[e3c + 1];

            float a0 = edge_mlp(qa0, qb0, ea0, wcp, w2r);
            float a1 = edge_mlp(qa1, qb1, eb0, wcp, w2r);
            reduce_store(ra0, ra1, re, lane, bias2, out);
            ra0 = a0;  ra1 = a1;  re = ec;

            ec = en;
            if (ec >= NUM_EDGES) break;
            en = e3;  enc = e3c;
        }

        qa0 = gatherA(ja.x, j0);  qb0 = gatherB(ja.y, j0);
        qa1 = gatherA(jb.x, j0);  qb1 = gatherB(jb.y, j0);
        ea0 = dist4[enc];  eb0 = dist4[enc + 1];
        {
            int e3  = en + stride;
            int e3c = (e3 < NUM_EDGES - 2) ? e3 : (NUM_EDGES - 2);
            ja = idx2[e3c];  jb = idx2[e3c + 1];

            float a0 = edge_mlp(pa0, pb0, da0, wcp, w2r);
            float a1 = edge_mlp(pa1, pb1, db0, wcp, w2r);
            reduce_store(ra0, ra1, re, lane, bias2, out);
            ra0 = a0;  ra1 = a1;  re = ec;

            ec = en;
            if (ec >= NUM_EDGES) break;
            en = e3;  enc = e3c;
        }
    }

    reduce_store(ra0, ra1, re, lane, bias2, out);
}

// ---------------------------------------------------------------------------
extern "C" void kernel_launch(void* const* d_in, const int* in_sizes, int n_in,
                              void* d_out, int out_size) {
    const float* x          = (const float*)d_in[0];
    const int*   edge_index = (const int*)d_in[1];
    const float* edge_dist  = (const float*)d_in[2];
    const float* w1         = (const float*)d_in[3];
    const float* b1         = (const float*)d_in[4];
    const float* w2         = (const float*)d_in[5];
    const float* b2         = (const float*)d_in[6];
    float*       out        = (float*)d_out;

    dim3 g1(8, (NUM_NODES + 127) / 128);   // (8, 79)
    precompute_mma<<<g1, 256>>>(x, w1, b1);

    edge_kernel<<<2368, 128>>>(edge_index, edge_dist, w1, w2, b2, out);
}

// round 13
// speedup vs baseline: 1.2241x; 1.1348x over previous
#include <cuda_runtime.h>
#include <cuda_bf16.h>
#include <stdint.h>

#define NUM_NODES 10000
#define NUM_EDGES 640000
#define GNN_IN    128
#define HID       256
#define NBLK      592          // 148 SMs x 4 resident blocks -- all wave-1
#define N_ITEMS   1256         // 157 m-tiles(64) x 8 n-tiles(64)

// Per-node tables: PAB[node][0:256]  = x[node]@W1[0:128] + b1  (b1 folded)
//                  PAB[node][256:512] = x[node]@W1[128:256]
__device__ __align__(16) __nv_bfloat16 g_pab[NUM_NODES * 512];

// Epoch grid-barrier counter: grows by exactly NBLK per launch, never reset.
__device__ unsigned g_bar;

// ---------------------------------------------------------------------------
// Helpers
// ---------------------------------------------------------------------------
__device__ __forceinline__ unsigned long long pack_f32x2(float lo, float hi) {
    unsigned long long r;
    asm("mov.b64 %0, {%1, %2};" : "=l"(r) : "f"(lo), "f"(hi));
    return r;
}
__device__ __forceinline__ void unpack_f32x2(unsigned long long v, float& lo, float& hi) {
    asm("mov.b64 {%0, %1}, %2;" : "=f"(lo), "=f"(hi) : "l"(v));
}
__device__ __forceinline__ unsigned long long fma_f32x2(
    unsigned long long a, unsigned long long b, unsigned long long c) {
    unsigned long long r;
    asm("fma.rn.f32x2 %0, %1, %2, %3;" : "=l"(r) : "l"(a), "l"(b), "l"(c));
    return r;
}
__device__ __forceinline__ uint32_t f32_to_tf32(float f) {
    uint32_t r;
    asm("cvt.rna.tf32.f32 %0, %1;" : "=r"(r) : "f"(f));
    return r;
}

__device__ __forceinline__ uint4 gatherA(int node, int j0) {
    return *(const uint4*)(g_pab + (size_t)node * 512 + j0);
}
__device__ __forceinline__ uint4 gatherB(int node, int j0) {
    return *(const uint4*)(g_pab + (size_t)node * 512 + 256 + j0);
}

__device__ __forceinline__ float edge_mlp(
    uint4 pa, uint4 pb, float4 d,
    const unsigned long long wcp[4][4], const float w2r[8])
{
    unsigned long long dd0 = pack_f32x2(d.x, d.x);
    unsigned long long dd1 = pack_f32x2(d.y, d.y);
    unsigned long long dd2 = pack_f32x2(d.z, d.z);
    unsigned long long dd3 = pack_f32x2(d.w, d.w);

    const unsigned* A = (const unsigned*)&pa;
    const unsigned* B = (const unsigned*)&pb;
    float accL = 0.f, accH = 0.f;
#pragma unroll
    for (int p = 0; p < 4; p++) {
        __nv_bfloat162 av = *(const __nv_bfloat162*)&A[p];
        __nv_bfloat162 bv = *(const __nv_bfloat162*)&B[p];
        __nv_bfloat162 sv = __hadd2(av, bv);
        unsigned w = *(const unsigned*)&sv;
        float lo = __uint_as_float(w << 16);
        float hi = __uint_as_float(w & 0xffff0000u);
        unsigned long long t2 = pack_f32x2(lo, hi);
        t2 = fma_f32x2(dd0, wcp[0][p], t2);
        t2 = fma_f32x2(dd1, wcp[1][p], t2);
        t2 = fma_f32x2(dd2, wcp[2][p], t2);
        t2 = fma_f32x2(dd3, wcp[3][p], t2);
        float t0, t1;
        unpack_f32x2(t2, t0, t1);
        t0 = fmaxf(t0, 0.f);
        t1 = fmaxf(t1, 0.f);
        accL = fmaf(t0, w2r[2 * p], accL);
        accH = fmaf(t1, w2r[2 * p + 1], accH);
    }
    return accL + accH;
}

__device__ __forceinline__ void reduce_store(
    float ra0, float ra1, int re, int lane, float bias2, float* out)
{
    float s0 = ra0 + __shfl_xor_sync(0xffffffffu, ra0, 16);
    float s1 = ra1 + __shfl_xor_sync(0xffffffffu, ra1, 16);
    float c  = (lane < 16) ? s0 : s1;
    c += __shfl_xor_sync(0xffffffffu, c, 8);
    c += __shfl_xor_sync(0xffffffffu, c, 4);
    c += __shfl_xor_sync(0xffffffffu, c, 2);
    c += __shfl_xor_sync(0xffffffffu, c, 1);
    if ((lane & 15) == 0) {
        float z = c + bias2;
        out[re + (lane >> 4)] = 1.f / (1.f + __expf(-z));
    }
}

// ---------------------------------------------------------------------------
// Fused persistent kernel: phase1 tf32-MMA precompute -> grid barrier ->
// phase2 edge MLP (R9 pipeline).
// ---------------------------------------------------------------------------
__global__ __launch_bounds__(128, 4) void fused_kernel(
    const float* __restrict__ x,
    const int*   __restrict__ edge_index,
    const float* __restrict__ edge_dist,
    const float* __restrict__ w1,
    const float* __restrict__ b1,
    const float* __restrict__ w2,
    const float* __restrict__ b2,
    float* __restrict__ out)
{
    __shared__ float Ws[128][68];   // 64-col W slice, pad 68: conflict-free LDS

    const int tid  = threadIdx.x;
    const int wid  = tid >> 5;      // 0..3
    const int lane = tid & 31;
    const int g    = lane >> 2;     // 0..7
    const int t    = lane & 3;      // 0..3

    // ===================== Phase 1: precompute GEMM =====================
    // Items b, b+592, b+1184 all share nt (592 % 8 == 0) -> stage Ws once.
    int prev_nt = -1;
    for (int item = blockIdx.x; item < N_ITEMS; item += NBLK) {
        const int nt = item & 7;
        const int mt = item >> 3;
        const int n0 = nt * 64;
        const int m0 = mt * 64 + wid * 16;

        const float* wbase = (n0 < 256) ? (w1 + n0)
                                        : (w1 + 128 * HID + (n0 - 256));
        if (nt != prev_nt) {
            if (prev_nt != -1) __syncthreads();   // drain readers of old Ws
#pragma unroll
            for (int i = 0; i < 16; i++) {
                int idx4 = i * 128 + tid;         // 0..2047 float4s
                int row  = idx4 >> 4;
                int c4   = idx4 & 15;
                float4 v = *(const float4*)(wbase + (size_t)row * HID + c4 * 4);
                *(float4*)&Ws[row][c4 * 4] = v;
            }
            __syncthreads();
            prev_nt = nt;
        }

        const int r0 = m0 + g, r1 = m0 + g + 8;
        const float* arow0 = x + (size_t)min(r0, NUM_NODES - 1) * GNN_IN;
        const float* arow1 = x + (size_t)min(r1, NUM_NODES - 1) * GNN_IN;

        float c[8][4];
#pragma unroll
        for (int nc = 0; nc < 8; nc++)
#pragma unroll
            for (int i = 0; i < 4; i++) c[nc][i] = 0.f;

#pragma unroll
        for (int ks = 0; ks < 16; ks++) {
            const int k0 = ks * 8;
            uint32_t a0 = f32_to_tf32(arow0[k0 + t]);
            uint32_t a1 = f32_to_tf32(arow1[k0 + t]);
            uint32_t a2 = f32_to_tf32(arow0[k0 + t + 4]);
            uint32_t a3 = f32_to_tf32(arow1[k0 + t + 4]);

#pragma unroll
            for (int nc = 0; nc < 8; nc++) {
                uint32_t b0  = f32_to_tf32(Ws[k0 + t][nc * 8 + g]);
                uint32_t b1v = f32_to_tf32(Ws[k0 + t + 4][nc * 8 + g]);
                asm("mma.sync.aligned.m16n8k8.row.col.f32.tf32.tf32.f32 "
                    "{%0,%1,%2,%3}, {%4,%5,%6,%7}, {%8,%9}, {%0,%1,%2,%3};"
                    : "+f"(c[nc][0]), "+f"(c[nc][1]), "+f"(c[nc][2]), "+f"(c[nc][3])
                    : "r"(a0), "r"(a1), "r"(a2), "r"(a3), "r"(b0), "r"(b1v));
            }
        }

#pragma unroll
        for (int nc = 0; nc < 8; nc++) {
            const int col = n0 + nc * 8 + 2 * t;
            float ba0 = 0.f, ba1 = 0.f;
            if (n0 < 256) { ba0 = b1[col]; ba1 = b1[col + 1]; }

            if (r0 < NUM_NODES) {
                __nv_bfloat162 p;
                p.x = __float2bfloat16_rn(c[nc][0] + ba0);
                p.y = __float2bfloat16_rn(c[nc][1] + ba1);
                *(__nv_bfloat162*)(g_pab + (size_t)r0 * 512 + col) = p;
            }
            if (r1 < NUM_NODES) {
                __nv_bfloat162 p;
                p.x = __float2bfloat16_rn(c[nc][2] + ba0);
                p.y = __float2bfloat16_rn(c[nc][3] + ba1);
                *(__nv_bfloat162*)(g_pab + (size_t)r1 * 512 + col) = p;
            }
        }
    }

    // === Edge-phase weight preload (independent of g_pab; hides in skew) ===
    const int j0 = lane * 8;
    unsigned long long wcp[4][4];
    float w2r[8];
#pragma unroll
    for (int i = 0; i < 8; i++) w2r[i] = w2[j0 + i];
#pragma unroll
    for (int r = 0; r < 4; r++)
#pragma unroll
        for (int p = 0; p < 4; p++)
            wcp[r][p] = pack_f32x2(w1[(size_t)(256 + r) * HID + j0 + 2 * p],
                                   w1[(size_t)(256 + r) * HID + j0 + 2 * p + 1]);
    const float bias2 = b2[0];

    // ===================== Grid barrier (epoch ticket) =====================
    __syncthreads();
    if (tid == 0) {
        __threadfence();                               // publish g_pab writes
        unsigned tkt = atomicAdd(&g_bar, 1u);
        unsigned target = (tkt / NBLK + 1u) * NBLK;    // end of this epoch
        unsigned v;
        do {
            asm volatile("ld.acquire.gpu.global.u32 %0, [%1];"
                         : "=r"(v) : "l"(&g_bar));
            if (v < target) __nanosleep(64);
        } while (v < target);
    }
    __syncthreads();

    // ===================== Phase 2: edge MLP (R9) =====================
    const int warp   = blockIdx.x * 4 + wid;
    const int nwarps = NBLK * 4;                       // 2368

    const int stride = nwarps * 2;
    int ec = warp * 2;
    if (ec >= NUM_EDGES) return;

    const int2*   idx2  = (const int2*)edge_index;
    const float4* dist4 = (const float4*)edge_dist;

    int en  = ec + stride;
    int enc = (en < NUM_EDGES - 2) ? en : (NUM_EDGES - 2);
    int2 ia = idx2[ec], ib = idx2[ec + 1];
    int2 ja = idx2[enc], jb = idx2[enc + 1];

    uint4 pa0 = gatherA(ia.x, j0), pb0 = gatherB(ia.y, j0);
    uint4 pa1 = gatherA(ib.x, j0), pb1 = gatherB(ib.y, j0);
    float4 da0 = dist4[ec], db0 = dist4[ec + 1];

    uint4 qa0 = gatherA(ja.x, j0), qb0 = gatherB(ja.y, j0);
    uint4 qa1 = gatherA(jb.x, j0), qb1 = gatherB(jb.y, j0);
    float4 ea0 = dist4[enc], eb0 = dist4[enc + 1];

    int e2  = en + stride;
    int e2c = (e2 < NUM_EDGES - 2) ? e2 : (NUM_EDGES - 2);
    ja = idx2[e2c];  jb = idx2[e2c + 1];

    float ra0 = edge_mlp(pa0, pb0, da0, wcp, w2r);
    float ra1 = edge_mlp(pa1, pb1, db0, wcp, w2r);
    int   re  = ec;

    ec = en;
    if (ec >= NUM_EDGES) {
        reduce_store(ra0, ra1, re, lane, bias2, out);
        return;
    }
    en = e2;  enc = e2c;

    for (;;) {
        pa0 = gatherA(ja.x, j0);  pb0 = gatherB(ja.y, j0);
        pa1 = gatherA(jb.x, j0);  pb1 = gatherB(jb.y, j0);
        da0 = dist4[enc];  db0 = dist4[enc + 1];
        {
            int e3  = en + stride;
            int e3c = (e3 < NUM_EDGES - 2) ? e3 : (NUM_EDGES - 2);
            ja = idx2[e3c];  jb = idx2[e3c + 1];

            float a0 = edge_mlp(qa0, qb0, ea0, wcp, w2r);
            float a1 = edge_mlp(qa1, qb1, eb0, wcp, w2r);
            reduce_store(ra0, ra1, re, lane, bias2, out);
            ra0 = a0;  ra1 = a1;  re = ec;

            ec = en;
            if (ec >= NUM_EDGES) break;
            en = e3;  enc = e3c;
        }

        qa0 = gatherA(ja.x, j0);  qb0 = gatherB(ja.y, j0);
        qa1 = gatherA(jb.x, j0);  qb1 = gatherB(jb.y, j0);
        ea0 = dist4[enc];  eb0 = dist4[enc + 1];
        {
            int e3  = en + stride;
            int e3c = (e3 < NUM_EDGES - 2) ? e3 : (NUM_EDGES - 2);
            ja = idx2[e3c];  jb = idx2[e3c + 1];

            float a0 = edge_mlp(pa0, pb0, da0, wcp, w2r);
            float a1 = edge_mlp(pa1, pb1, db0, wcp, w2r);
            reduce_store(ra0, ra1, re, lane, bias2, out);
            ra0 = a0;  ra1 = a1;  re = ec;

            ec = en;
            if (ec >= NUM_EDGES) break;
            en = e3;  enc = e3c;
        }
    }

    reduce_store(ra0, ra1, re, lane, bias2, out);
}

// ---------------------------------------------------------------------------
extern "C" void kernel_launch(void* const* d_in, const int* in_sizes, int n_in,
                              void* d_out, int out_size) {
    const float* x          = (const float*)d_in[0];
    const int*   edge_index = (const int*)d_in[1];
    const float* edge_dist  = (const float*)d_in[2];
    const float* w1         = (const float*)d_in[3];
    const float* b1         = (const float*)d_in[4];
    const float* w2         = (const float*)d_in[5];
    const float* b2         = (const float*)d_in[6];
    float*       out        = (float*)d_out;

    fused_kernel<<<NBLK, 128>>>(x, edge_index, edge_dist, w1, b1, w2, b2, out);
}